// round 1
// baseline (speedup 1.0000x reference)
#include <cuda_runtime.h>

#define B_TOT 4096
#define HID 128
#define NCELL 81
#define LN_EPS 1e-5f

// ---------------- static device workspace (no allocations allowed) ----------
__device__ float g_h[NCELL][B_TOT][HID];
__device__ float g_c[NCELL][B_TOT][HID];
__device__ float g_z [B_TOT][256];
__device__ float g_y1[B_TOT][256];
__device__ float g_y2[B_TOT][128];
__device__ float g_y3[B_TOT];
__device__ float g_mu[256];
__device__ float g_rstd[256];

__device__ __forceinline__ float sigmf(float v) { return 1.f / (1.f + expf(-v)); }

// ---------------------------------------------------------------------------
// Per-cell fused kernel. One CTA = 64 batch rows. 256 threads, thread tile 4x8.
// smem (floats): A_s 64*33=2112 | W_s 512*33=16896 | ph_s 64*133=8512 | pc_s 8512
#define SM_A   0
#define SM_W   2112
#define SM_PH  (2112 + 16896)
#define SM_PC  (SM_PH + 8512)
#define CELL_SMEM_FLOATS (SM_PC + 8512)
#define CELL_SMEM_BYTES (CELL_SMEM_FLOATS * 4)

// GEMM [64,384] x [384,128]^T + bias, then LayerNorm over the 128 cols, into out_s.
__device__ __forceinline__ void gemm_ln(
    const float* s0, const float* s1, const float* s2,   // concat sources (may be null = zeros)
    const float* __restrict__ Wk, const float* __restrict__ biask,
    const float* __restrict__ lng, const float* __restrict__ lnb,
    float* A_s, float* W_s, float* out_s,
    int tid, int ty, int tx, int b0)
{
    float acc[4][8];
#pragma unroll
    for (int r = 0; r < 4; r++)
#pragma unroll
        for (int c = 0; c < 8; c++) acc[r][c] = 0.f;

    const float* srcs[3] = { s0, s1, s2 };

#pragma unroll 1
    for (int kc = 0; kc < 12; kc++) {
        const float* s = srcs[kc >> 2];
        int colb = (kc & 3) << 5;
        // load A tile 64x32
#pragma unroll
        for (int it = 0; it < 2; it++) {
            int idx = it * 256 + tid;           // 0..511 float4 slots
            int r = idx >> 3; int c4 = (idx & 7) << 2;
            float4 v = make_float4(0.f, 0.f, 0.f, 0.f);
            if (s) v = *(const float4*)(s + (size_t)(b0 + r) * HID + colb + c4);
            float* p = &A_s[r * 33 + c4];
            p[0] = v.x; p[1] = v.y; p[2] = v.z; p[3] = v.w;
        }
        // load W tile 128x32 (row stride 384)
#pragma unroll
        for (int it = 0; it < 4; it++) {
            int idx = it * 256 + tid;           // 0..1023
            int n = idx >> 3; int c4 = (idx & 7) << 2;
            float4 v = *(const float4*)(Wk + n * 384 + (kc << 5) + c4);
            float* p = &W_s[n * 33 + c4];
            p[0] = v.x; p[1] = v.y; p[2] = v.z; p[3] = v.w;
        }
        __syncthreads();
#pragma unroll 4
        for (int kk = 0; kk < 32; kk++) {
            float a[4], w[8];
#pragma unroll
            for (int r = 0; r < 4; r++) a[r] = A_s[(ty * 4 + r) * 33 + kk];
#pragma unroll
            for (int c = 0; c < 8; c++) w[c] = W_s[(tx * 8 + c) * 33 + kk];
#pragma unroll
            for (int r = 0; r < 4; r++)
#pragma unroll
                for (int c = 0; c < 8; c++) acc[r][c] = fmaf(a[r], w[c], acc[r][c]);
        }
        __syncthreads();
    }
    // bias + stage for LN
#pragma unroll
    for (int r = 0; r < 4; r++)
#pragma unroll
        for (int c = 0; c < 8; c++)
            out_s[(ty * 4 + r) * 133 + tx * 8 + c] = acc[r][c] + biask[tx * 8 + c];
    __syncthreads();

    // LayerNorm: warp handles 8 rows, lane covers 4 cols
    int warp = tid >> 5, lane = tid & 31;
#pragma unroll 1
    for (int rr = 0; rr < 8; rr++) {
        int r = warp * 8 + rr;
        float v0 = out_s[r * 133 + lane];
        float v1 = out_s[r * 133 + lane + 32];
        float v2 = out_s[r * 133 + lane + 64];
        float v3 = out_s[r * 133 + lane + 96];
        float s = v0 + v1 + v2 + v3;
        float q = v0 * v0 + v1 * v1 + v2 * v2 + v3 * v3;
#pragma unroll
        for (int o = 16; o; o >>= 1) {
            s += __shfl_xor_sync(0xffffffffu, s, o);
            q += __shfl_xor_sync(0xffffffffu, q, o);
        }
        float mu = s * (1.f / 128.f);
        float var = q * (1.f / 128.f) - mu * mu;
        float rs = rsqrtf(var + LN_EPS);
        out_s[r * 133 + lane]      = (v0 - mu) * rs * lng[lane]      + lnb[lane];
        out_s[r * 133 + lane + 32] = (v1 - mu) * rs * lng[lane + 32] + lnb[lane + 32];
        out_s[r * 133 + lane + 64] = (v2 - mu) * rs * lng[lane + 64] + lnb[lane + 64];
        out_s[r * 133 + lane + 96] = (v3 - mu) * rs * lng[lane + 96] + lnb[lane + 96];
    }
    __syncthreads();
}

__global__ void __launch_bounds__(256, 1) cell_kernel(
    const float* __restrict__ x,
    const float* __restrict__ h_ext, const float* __restrict__ c_ext,
    const float* __restrict__ h_grid0, const float* __restrict__ c_grid0,
    const float* __restrict__ Wh, const float* __restrict__ bh,
    const float* __restrict__ Wc, const float* __restrict__ bc,
    const float* __restrict__ lnh_g, const float* __restrict__ lnh_b,
    const float* __restrict__ lnc_g, const float* __restrict__ lnc_b,
    const float* __restrict__ W_ih, const float* __restrict__ b_ih,
    const float* __restrict__ W_hh, const float* __restrict__ b_hh,
    int diag)
{
    extern __shared__ float sm[];
    float* A_s  = sm + SM_A;
    float* W_s  = sm + SM_W;
    float* ph_s = sm + SM_PH;
    float* pc_s = sm + SM_PC;

    int tid = threadIdx.x, ty = tid & 15, tx = tid >> 4;
    int b0 = blockIdx.x << 6;

    int i0 = diag > 8 ? diag - 8 : 0;
    int i = i0 + blockIdx.y;
    int j = diag - i;
    int k = i * 9 + j;

    const float *h0, *c0, *h1, *c1;
    if (j > 0)       { h0 = &g_h[k - 1][0][0]; c0 = &g_c[k - 1][0][0]; }
    else if (i == 0) { h0 = h_ext;             c0 = c_ext; }
    else             { h0 = 0;                 c0 = 0; }
    if (i > 0)       { h1 = &g_h[k - 9][0][0]; c1 = &g_c[k - 9][0][0]; }
    else             { h1 = 0;                 c1 = 0; }
    const float* h2 = h_grid0 + (size_t)k * B_TOT * HID;
    const float* c2 = c_grid0 + (size_t)k * B_TOT * HID;

    gemm_ln(h0, h1, h2, Wh + (size_t)k * 128 * 384, bh + k * 128,
            lnh_g + k * 128, lnh_b + k * 128, A_s, W_s, ph_s, tid, ty, tx, b0);
    gemm_ln(c0, c1, c2, Wc + (size_t)k * 128 * 384, bc + k * 128,
            lnc_g + k * 128, lnc_b + k * 128, A_s, W_s, pc_s, tid, ty, tx, b0);

    // ---- gates GEMM: [64,128] (ph_s) x [128,512]^T, all 4 gate chunks in regs
    const float* Whh = W_hh + (size_t)k * 512 * 128;
    float accG[4][4][8];
#pragma unroll
    for (int g = 0; g < 4; g++)
#pragma unroll
        for (int r = 0; r < 4; r++)
#pragma unroll
            for (int c = 0; c < 8; c++) accG[g][r][c] = 0.f;

#pragma unroll 1
    for (int kc = 0; kc < 4; kc++) {
#pragma unroll
        for (int it = 0; it < 16; it++) {
            int idx = it * 256 + tid;         // 0..4095 float4 slots
            int m = idx >> 3;                 // 0..511 (gate row)
            int c4 = (idx & 7) << 2;
            float4 v = *(const float4*)(Whh + m * 128 + (kc << 5) + c4);
            float* p = &W_s[m * 33 + c4];
            p[0] = v.x; p[1] = v.y; p[2] = v.z; p[3] = v.w;
        }
        __syncthreads();
#pragma unroll 2
        for (int kk = 0; kk < 32; kk++) {
            float a[4];
#pragma unroll
            for (int r = 0; r < 4; r++) a[r] = ph_s[(ty * 4 + r) * 133 + (kc << 5) + kk];
#pragma unroll
            for (int g = 0; g < 4; g++)
#pragma unroll
                for (int c = 0; c < 8; c++) {
                    float w = W_s[(g * 128 + tx * 8 + c) * 33 + kk];
#pragma unroll
                    for (int r = 0; r < 4; r++)
                        accG[g][r][c] = fmaf(a[r], w, accG[g][r][c]);
                }
        }
        __syncthreads();
    }

    // ---- LSTM elementwise
    const float* bih = b_ih + k * 512;
    const float* bhh = b_hh + k * 512;
    const float* wih = W_ih + k * 512;
#pragma unroll
    for (int r = 0; r < 4; r++) {
        int row = ty * 4 + r;
        float xb = x[(size_t)(b0 + row) * 81 + k];
#pragma unroll
        for (int c = 0; c < 8; c++) {
            int col = tx * 8 + c;
            float ig = accG[0][r][c] + bih[col]       + bhh[col]       + xb * wih[col];
            float fg = accG[1][r][c] + bih[128 + col] + bhh[128 + col] + xb * wih[128 + col];
            float gg = accG[2][r][c] + bih[256 + col] + bhh[256 + col] + xb * wih[256 + col];
            float og = accG[3][r][c] + bih[384 + col] + bhh[384 + col] + xb * wih[384 + col];
            float pcv = pc_s[row * 133 + col];
            float cn = sigmf(fg) * pcv + sigmf(ig) * tanhf(gg);
            float hn = sigmf(og) * tanhf(cn);
            pc_s[row * 133 + col] = cn;
            ph_s[row * 133 + col] = hn;
        }
    }
    __syncthreads();

    // ---- coalesced writeout
    float* gh = &g_h[k][b0][0];
    float* gc = &g_c[k][b0][0];
#pragma unroll
    for (int it = 0; it < 8; it++) {
        int idx = it * 256 + tid;             // float4 slots 0..2047
        int r = idx >> 5; int c4 = (idx & 31) << 2;
        float4 vh = make_float4(ph_s[r * 133 + c4],     ph_s[r * 133 + c4 + 1],
                                ph_s[r * 133 + c4 + 2], ph_s[r * 133 + c4 + 3]);
        float4 vc = make_float4(pc_s[r * 133 + c4],     pc_s[r * 133 + c4 + 1],
                                pc_s[r * 133 + c4 + 2], pc_s[r * 133 + c4 + 3]);
        *(float4*)(gh + r * HID + c4) = vh;
        *(float4*)(gc + r * HID + c4) = vc;
    }
}

// ---------------------------------------------------------------------------
// Head kernels
__global__ void z_kernel(const float* __restrict__ h_ext, const float* __restrict__ c_ext)
{
    int idx = blockIdx.x * 256 + threadIdx.x;
    int b = idx >> 8, c = idx & 255;
    float v;
    if (c < 128) v = g_h[80][b][c]       + h_ext[b * 128 + c];
    else         v = g_c[80][b][c - 128] + c_ext[b * 128 + c - 128];
    g_z[b][c] = v;
}

__global__ void __launch_bounds__(256, 1) head_gemm(
    const float* __restrict__ A, const float* __restrict__ W,
    const float* __restrict__ bias, float* __restrict__ C, int N, int K)
{
    __shared__ float A_s[64 * 33];
    __shared__ float W_s[128 * 33];
    int tid = threadIdx.x, ty = tid & 15, tx = tid >> 4;
    int b0 = blockIdx.x * 64, n0 = blockIdx.y * 128;
    float acc[4][8];
#pragma unroll
    for (int r = 0; r < 4; r++)
#pragma unroll
        for (int c = 0; c < 8; c++) acc[r][c] = 0.f;

    int nk = K >> 5;
#pragma unroll 1
    for (int kc = 0; kc < nk; kc++) {
#pragma unroll
        for (int it = 0; it < 2; it++) {
            int idx = it * 256 + tid; int r = idx >> 3; int c4 = (idx & 7) << 2;
            float4 v = *(const float4*)(A + (size_t)(b0 + r) * K + (kc << 5) + c4);
            float* p = &A_s[r * 33 + c4];
            p[0] = v.x; p[1] = v.y; p[2] = v.z; p[3] = v.w;
        }
#pragma unroll
        for (int it = 0; it < 4; it++) {
            int idx = it * 256 + tid; int n = idx >> 3; int c4 = (idx & 7) << 2;
            float4 v = *(const float4*)(W + (size_t)(n0 + n) * K + (kc << 5) + c4);
            float* p = &W_s[n * 33 + c4];
            p[0] = v.x; p[1] = v.y; p[2] = v.z; p[3] = v.w;
        }
        __syncthreads();
#pragma unroll 4
        for (int kk = 0; kk < 32; kk++) {
            float a[4], w[8];
#pragma unroll
            for (int r = 0; r < 4; r++) a[r] = A_s[(ty * 4 + r) * 33 + kk];
#pragma unroll
            for (int c = 0; c < 8; c++) w[c] = W_s[(tx * 8 + c) * 33 + kk];
#pragma unroll
            for (int r = 0; r < 4; r++)
#pragma unroll
                for (int c = 0; c < 8; c++) acc[r][c] = fmaf(a[r], w[c], acc[r][c]);
        }
        __syncthreads();
    }
#pragma unroll
    for (int r = 0; r < 4; r++)
#pragma unroll
        for (int c = 0; c < 8; c++)
            C[(size_t)(b0 + ty * 4 + r) * N + n0 + tx * 8 + c] = acc[r][c] + bias[n0 + tx * 8 + c];
}

__global__ void bn_stats_kernel(const float* __restrict__ Y, int N)
{
    __shared__ float ss[256], qq[256];
    int col = blockIdx.x, tid = threadIdx.x;
    float s = 0.f, q = 0.f;
    for (int r = tid; r < B_TOT; r += 256) {
        float v = Y[(size_t)r * N + col];
        s += v; q += v * v;
    }
    ss[tid] = s; qq[tid] = q; __syncthreads();
    for (int o = 128; o; o >>= 1) {
        if (tid < o) { ss[tid] += ss[tid + o]; qq[tid] += qq[tid + o]; }
        __syncthreads();
    }
    if (tid == 0) {
        float mu = ss[0] * (1.f / (float)B_TOT);
        float var = qq[0] * (1.f / (float)B_TOT) - mu * mu;
        g_mu[col] = mu;
        g_rstd[col] = rsqrtf(var + LN_EPS);
    }
}

__global__ void bn_relu_kernel(float* __restrict__ Y, const float* __restrict__ g,
                               const float* __restrict__ b, int N)
{
    int idx = blockIdx.x * 256 + threadIdx.x;
    int c = idx & (N - 1);
    float v = (Y[idx] - g_mu[c]) * g_rstd[c] * g[c] + b[c];
    Y[idx] = fmaxf(v, 0.f);
}

__global__ void fc3_kernel(const float* __restrict__ W, const float* __restrict__ bias)
{
    int row = (blockIdx.x * blockDim.x + threadIdx.x) >> 5;
    int lane = threadIdx.x & 31;
    float s = 0.f;
#pragma unroll
    for (int c = lane; c < 128; c += 32) s += g_y2[row][c] * W[c];
#pragma unroll
    for (int o = 16; o; o >>= 1) s += __shfl_xor_sync(0xffffffffu, s, o);
    if (lane == 0) g_y3[row] = s + bias[0];
}

__global__ void final_kernel(const float* __restrict__ g, const float* __restrict__ b,
                             float* __restrict__ out)
{
    __shared__ float ss[1024], qq[1024];
    int tid = threadIdx.x;
    float s = 0.f, q = 0.f;
    for (int r = tid; r < B_TOT; r += 1024) {
        float v = g_y3[r]; s += v; q += v * v;
    }
    ss[tid] = s; qq[tid] = q; __syncthreads();
    for (int o = 512; o; o >>= 1) {
        if (tid < o) { ss[tid] += ss[tid + o]; qq[tid] += qq[tid + o]; }
        __syncthreads();
    }
    float mu = ss[0] * (1.f / (float)B_TOT);
    float var = qq[0] * (1.f / (float)B_TOT) - mu * mu;
    float rs = rsqrtf(var + LN_EPS);
    float gg = g[0], bb = b[0];
    for (int r = tid; r < B_TOT; r += 1024) {
        float v = (g_y3[r] - mu) * rs * gg + bb;
        out[r] = 1.f / (1.f + expf(-v));
    }
}

// ---------------------------------------------------------------------------
extern "C" void kernel_launch(void* const* d_in, const int* in_sizes, int n_in,
                              void* d_out, int out_size)
{
    const float* x     = (const float*)d_in[0];
    const float* h_ext = (const float*)d_in[1];
    const float* c_ext = (const float*)d_in[2];
    const float* h_g0  = (const float*)d_in[3];
    const float* c_g0  = (const float*)d_in[4];
    const float* Wh    = (const float*)d_in[5];
    const float* bh    = (const float*)d_in[6];
    const float* Wc    = (const float*)d_in[7];
    const float* bc    = (const float*)d_in[8];
    const float* lnh_g = (const float*)d_in[9];
    const float* lnh_b = (const float*)d_in[10];
    const float* lnc_g = (const float*)d_in[11];
    const float* lnc_b = (const float*)d_in[12];
    const float* W_ih  = (const float*)d_in[13];
    const float* b_ih  = (const float*)d_in[14];
    const float* W_hh  = (const float*)d_in[15];
    const float* b_hh  = (const float*)d_in[16];
    const float* fc1W  = (const float*)d_in[17];
    const float* fc1b  = (const float*)d_in[18];
    const float* bn1g  = (const float*)d_in[19];
    const float* bn1b  = (const float*)d_in[20];
    const float* fc2W  = (const float*)d_in[21];
    const float* fc2b  = (const float*)d_in[22];
    const float* bn2g  = (const float*)d_in[23];
    const float* bn2b  = (const float*)d_in[24];
    const float* fc3W  = (const float*)d_in[25];
    const float* fc3b  = (const float*)d_in[26];
    const float* bnog  = (const float*)d_in[27];
    const float* bnob  = (const float*)d_in[28];
    float* out = (float*)d_out;

    cudaFuncSetAttribute(cell_kernel, cudaFuncAttributeMaxDynamicSharedMemorySize,
                         CELL_SMEM_BYTES);

    for (int d = 0; d <= 16; d++) {
        int ilo = d > 8 ? d - 8 : 0;
        int ihi = d < 8 ? d : 8;
        int nc = ihi - ilo + 1;
        cell_kernel<<<dim3(64, nc), 256, CELL_SMEM_BYTES>>>(
            x, h_ext, c_ext, h_g0, c_g0, Wh, bh, Wc, bc,
            lnh_g, lnh_b, lnc_g, lnc_b, W_ih, b_ih, W_hh, b_hh, d);
    }

    float *zp, *y1p, *y2p;
    cudaGetSymbolAddress((void**)&zp,  g_z);
    cudaGetSymbolAddress((void**)&y1p, g_y1);
    cudaGetSymbolAddress((void**)&y2p, g_y2);

    z_kernel<<<4096, 256>>>(h_ext, c_ext);
    head_gemm<<<dim3(64, 2), 256>>>(zp, fc1W, fc1b, y1p, 256, 256);
    bn_stats_kernel<<<256, 256>>>(y1p, 256);
    bn_relu_kernel<<<4096, 256>>>(y1p, bn1g, bn1b, 256);
    head_gemm<<<dim3(64, 1), 256>>>(y1p, fc2W, fc2b, y2p, 128, 256);
    bn_stats_kernel<<<128, 256>>>(y2p, 128);
    bn_relu_kernel<<<2048, 256>>>(y2p, bn2g, bn2b, 128);
    fc3_kernel<<<512, 256>>>(fc3W, fc3b);
    final_kernel<<<1, 1024>>>(bnog, bnob, out);
}

// round 2
// speedup vs baseline: 1.3472x; 1.3472x over previous
#include <cuda_runtime.h>

#define B_TOT 4096
#define HID 128
#define NCELL 81
#define LN_EPS 1e-5f

typedef unsigned long long ull;

__device__ __forceinline__ ull ffma2(ull a, ull b, ull c) {
    ull d; asm("fma.rn.f32x2 %0, %1, %2, %3;" : "=l"(d) : "l"(a), "l"(b), "l"(c)); return d;
}
__device__ __forceinline__ ull pack2(float x, float y) {
    ull d; asm("mov.b64 %0, {%1, %2};" : "=l"(d) : "f"(x), "f"(y)); return d;
}
__device__ __forceinline__ float2 unpk(ull v) {
    float2 r; asm("mov.b64 {%0, %1}, %2;" : "=f"(r.x), "=f"(r.y) : "l"(v)); return r;
}
union F4 { float4 f; ull u[2]; };

// ---------------- static device workspace ----------------
__device__ float g_h[NCELL][B_TOT][HID];
__device__ float g_c[NCELL][B_TOT][HID];
__device__ float g_z [B_TOT][256];
__device__ float g_y1[B_TOT][256];
__device__ float g_y2[B_TOT][128];
__device__ float g_y3[B_TOT];
__device__ float g_mu[256];
__device__ float g_rstd[256];

__device__ __forceinline__ float sigmf(float v) { return 1.f / (1.f + expf(-v)); }

// ---------------- smem layout (floats) ----------------
// ph_s: 64x133, pc_s: 64x133, scratch: max(gemm A_T/W_T double buf, gates G_T double buf)
#define PP 133
#define PA 66     // A_T pitch (k-major, 32 x 64)
#define PW 132    // W_T pitch (k-major, 32 x 128)
#define PG 516    // gates G_T pitch (k-major, 32 x 512)
#define SM_PH  0
#define SM_PC  (64 * PP)
#define SM_SCR (2 * 64 * PP)            // 17024
#define ACH (32 * PA)                   // 2112 per A buf
#define WCH (32 * PW)                   // 4224 per W buf
#define GCH (32 * PG)                   // 16512 per gates buf
#define CELL_SMEM_FLOATS (SM_SCR + 2 * GCH)   // 17024 + 33024 = 50048
#define CELL_SMEM_BYTES (CELL_SMEM_FLOATS * 4)

// ---------------------------------------------------------------------------
// GEMM [64,384]x[384,128]^T + bias + LayerNorm -> out_s (pitch PP)
// threads: ty = tid&15 (rows 4ty..), tx = tid>>4 (cols 8tx..)
__device__ __forceinline__ void gemm_ln(
    const float* s0, const float* s1, const float* s2,
    const float* __restrict__ Wk, const float* __restrict__ biask,
    const float* __restrict__ lng, const float* __restrict__ lnb,
    float* AT0, float* WT0, float* out_s,
    int tid, int ty, int tx, int b0)
{
    ull acc[4][4];
#pragma unroll
    for (int r = 0; r < 4; r++)
#pragma unroll
        for (int q = 0; q < 4; q++) acc[r][q] = 0ull;

    const float* srcs[3] = { s0, s1, s2 };

    // prologue: chunk 0 direct load
    {
        const float* s = srcs[0];
#pragma unroll
        for (int it = 0; it < 2; it++) {
            int idx = it * 256 + tid; int row = idx >> 3; int c4 = (idx & 7) << 2;
            float4 v = make_float4(0.f, 0.f, 0.f, 0.f);
            if (s) v = *(const float4*)(s + (size_t)(b0 + row) * HID + c4);
            AT0[(c4 + 0) * PA + row] = v.x; AT0[(c4 + 1) * PA + row] = v.y;
            AT0[(c4 + 2) * PA + row] = v.z; AT0[(c4 + 3) * PA + row] = v.w;
        }
#pragma unroll
        for (int it = 0; it < 4; it++) {
            int idx = it * 256 + tid; int n = idx >> 3; int c4 = (idx & 7) << 2;
            float4 v = *(const float4*)(Wk + n * 384 + c4);
            WT0[(c4 + 0) * PW + n] = v.x; WT0[(c4 + 1) * PW + n] = v.y;
            WT0[(c4 + 2) * PW + n] = v.z; WT0[(c4 + 3) * PW + n] = v.w;
        }
    }
    __syncthreads();

#pragma unroll 1
    for (int kc = 0; kc < 12; kc++) {
        // prefetch next chunk into registers
        float4 rA[2], rW[4];
        bool pre = (kc < 11);
        if (pre) {
            int kn = kc + 1;
            const float* s = srcs[kn >> 2];
            int colb = (kn & 3) << 5;
#pragma unroll
            for (int it = 0; it < 2; it++) {
                int idx = it * 256 + tid; int row = idx >> 3; int c4 = (idx & 7) << 2;
                rA[it] = make_float4(0.f, 0.f, 0.f, 0.f);
                if (s) rA[it] = *(const float4*)(s + (size_t)(b0 + row) * HID + colb + c4);
            }
#pragma unroll
            for (int it = 0; it < 4; it++) {
                int idx = it * 256 + tid; int n = idx >> 3; int c4 = (idx & 7) << 2;
                rW[it] = *(const float4*)(Wk + n * 384 + (kn << 5) + c4);
            }
        }

        const float* AT = AT0 + (kc & 1) * ACH;
        const float* WT = WT0 + (kc & 1) * WCH;
#pragma unroll 8
        for (int kk = 0; kk < 32; kk++) {
            const float* at = AT + kk * PA + 4 * ty;
            float2 a01 = *(const float2*)at;
            float2 a23 = *(const float2*)(at + 2);
            ull aa[4];
            aa[0] = pack2(a01.x, a01.x); aa[1] = pack2(a01.y, a01.y);
            aa[2] = pack2(a23.x, a23.x); aa[3] = pack2(a23.y, a23.y);
            const float* wt = WT + kk * PW + 8 * tx;
            F4 w0, w1; w0.f = *(const float4*)wt; w1.f = *(const float4*)(wt + 4);
#pragma unroll
            for (int r = 0; r < 4; r++) {
                acc[r][0] = ffma2(aa[r], w0.u[0], acc[r][0]);
                acc[r][1] = ffma2(aa[r], w0.u[1], acc[r][1]);
                acc[r][2] = ffma2(aa[r], w1.u[0], acc[r][2]);
                acc[r][3] = ffma2(aa[r], w1.u[1], acc[r][3]);
            }
        }

        if (pre) {
            float* ATn = AT0 + ((kc + 1) & 1) * ACH;
            float* WTn = WT0 + ((kc + 1) & 1) * WCH;
#pragma unroll
            for (int it = 0; it < 2; it++) {
                int idx = it * 256 + tid; int row = idx >> 3; int c4 = (idx & 7) << 2;
                ATn[(c4 + 0) * PA + row] = rA[it].x; ATn[(c4 + 1) * PA + row] = rA[it].y;
                ATn[(c4 + 2) * PA + row] = rA[it].z; ATn[(c4 + 3) * PA + row] = rA[it].w;
            }
#pragma unroll
            for (int it = 0; it < 4; it++) {
                int idx = it * 256 + tid; int n = idx >> 3; int c4 = (idx & 7) << 2;
                WTn[(c4 + 0) * PW + n] = rW[it].x; WTn[(c4 + 1) * PW + n] = rW[it].y;
                WTn[(c4 + 2) * PW + n] = rW[it].z; WTn[(c4 + 3) * PW + n] = rW[it].w;
            }
        }
        __syncthreads();
    }

    // bias + stage for LN
#pragma unroll
    for (int r = 0; r < 4; r++)
#pragma unroll
        for (int q = 0; q < 4; q++) {
            float2 v = unpk(acc[r][q]);
            int col = 8 * tx + 2 * q;
            out_s[(ty * 4 + r) * PP + col]     = v.x + biask[col];
            out_s[(ty * 4 + r) * PP + col + 1] = v.y + biask[col + 1];
        }
    __syncthreads();

    int warp = tid >> 5, lane = tid & 31;
#pragma unroll 1
    for (int rr = 0; rr < 8; rr++) {
        int r = warp * 8 + rr;
        float v0 = out_s[r * PP + lane];
        float v1 = out_s[r * PP + lane + 32];
        float v2 = out_s[r * PP + lane + 64];
        float v3 = out_s[r * PP + lane + 96];
        float s = v0 + v1 + v2 + v3;
        float q = v0 * v0 + v1 * v1 + v2 * v2 + v3 * v3;
#pragma unroll
        for (int o = 16; o; o >>= 1) {
            s += __shfl_xor_sync(0xffffffffu, s, o);
            q += __shfl_xor_sync(0xffffffffu, q, o);
        }
        float mu = s * (1.f / 128.f);
        float var = q * (1.f / 128.f) - mu * mu;
        float rs = rsqrtf(var + LN_EPS);
        out_s[r * PP + lane]      = (v0 - mu) * rs * lng[lane]      + lnb[lane];
        out_s[r * PP + lane + 32] = (v1 - mu) * rs * lng[lane + 32] + lnb[lane + 32];
        out_s[r * PP + lane + 64] = (v2 - mu) * rs * lng[lane + 64] + lnb[lane + 64];
        out_s[r * PP + lane + 96] = (v3 - mu) * rs * lng[lane + 96] + lnb[lane + 96];
    }
    __syncthreads();
}

__device__ __forceinline__ void loadG(const float* __restrict__ Whh, int kc,
                                      float* GT, int tid)
{
#pragma unroll
    for (int it = 0; it < 16; it++) {
        int idx = it * 256 + tid;
        int m = idx >> 3; int c4 = (idx & 7) << 2;
        float4 v = *(const float4*)(Whh + m * 128 + (kc << 5) + c4);
        GT[(c4 + 0) * PG + m] = v.x; GT[(c4 + 1) * PG + m] = v.y;
        GT[(c4 + 2) * PG + m] = v.z; GT[(c4 + 3) * PG + m] = v.w;
    }
}

__global__ void __launch_bounds__(256) cell_kernel(
    const float* __restrict__ x,
    const float* __restrict__ h_ext, const float* __restrict__ c_ext,
    const float* __restrict__ h_grid0, const float* __restrict__ c_grid0,
    const float* __restrict__ Wh, const float* __restrict__ bh,
    const float* __restrict__ Wc, const float* __restrict__ bc,
    const float* __restrict__ lnh_g, const float* __restrict__ lnh_b,
    const float* __restrict__ lnc_g, const float* __restrict__ lnc_b,
    const float* __restrict__ W_ih, const float* __restrict__ b_ih,
    const float* __restrict__ W_hh, const float* __restrict__ b_hh,
    int diag)
{
    extern __shared__ float sm[];
    float* ph_s = sm + SM_PH;
    float* pc_s = sm + SM_PC;
    float* AT0  = sm + SM_SCR;
    float* WT0  = sm + SM_SCR + 2 * ACH;
    float* GT0  = sm + SM_SCR;

    int tid = threadIdx.x, ty = tid & 15, tx = tid >> 4;
    int b0 = blockIdx.x << 6;

    int i0 = diag > 8 ? diag - 8 : 0;
    int i = i0 + blockIdx.y;
    int j = diag - i;
    int k = i * 9 + j;

    const float *h0, *c0, *h1, *c1;
    if (j > 0)       { h0 = &g_h[k - 1][0][0]; c0 = &g_c[k - 1][0][0]; }
    else if (i == 0) { h0 = h_ext;             c0 = c_ext; }
    else             { h0 = 0;                 c0 = 0; }
    if (i > 0)       { h1 = &g_h[k - 9][0][0]; c1 = &g_c[k - 9][0][0]; }
    else             { h1 = 0;                 c1 = 0; }
    const float* h2 = h_grid0 + (size_t)k * B_TOT * HID;
    const float* c2 = c_grid0 + (size_t)k * B_TOT * HID;

    gemm_ln(h0, h1, h2, Wh + (size_t)k * 128 * 384, bh + k * 128,
            lnh_g + k * 128, lnh_b + k * 128, AT0, WT0, ph_s, tid, ty, tx, b0);
    gemm_ln(c0, c1, c2, Wc + (size_t)k * 128 * 384, bc + k * 128,
            lnc_g + k * 128, lnc_b + k * 128, AT0, WT0, pc_s, tid, ty, tx, b0);

    // ---- gates GEMM: [64,128] (ph_s) x [128,512]^T, packed accumulators
    const float* Whh = W_hh + (size_t)k * 512 * 128;
    ull accG[4][4][4];
#pragma unroll
    for (int g = 0; g < 4; g++)
#pragma unroll
        for (int r = 0; r < 4; r++)
#pragma unroll
            for (int q = 0; q < 4; q++) accG[g][r][q] = 0ull;

    loadG(Whh, 0, GT0, tid);
    __syncthreads();

#pragma unroll 1
    for (int kc = 0; kc < 4; kc++) {
        if (kc < 3) loadG(Whh, kc + 1, GT0 + ((kc + 1) & 1) * GCH, tid);
        const float* GT = GT0 + (kc & 1) * GCH;
        int kcb = kc << 5;
#pragma unroll 2
        for (int kk = 0; kk < 32; kk++) {
            ull aa[4];
#pragma unroll
            for (int r = 0; r < 4; r++) {
                float a = ph_s[(4 * ty + r) * PP + kcb + kk];
                aa[r] = pack2(a, a);
            }
#pragma unroll
            for (int g = 0; g < 4; g++) {
                const float* wt = GT + kk * PG + g * 128 + 8 * tx;
                F4 w0, w1; w0.f = *(const float4*)wt; w1.f = *(const float4*)(wt + 4);
#pragma unroll
                for (int r = 0; r < 4; r++) {
                    accG[g][r][0] = ffma2(aa[r], w0.u[0], accG[g][r][0]);
                    accG[g][r][1] = ffma2(aa[r], w0.u[1], accG[g][r][1]);
                    accG[g][r][2] = ffma2(aa[r], w1.u[0], accG[g][r][2]);
                    accG[g][r][3] = ffma2(aa[r], w1.u[1], accG[g][r][3]);
                }
            }
        }
        __syncthreads();
    }

    // ---- LSTM elementwise
    const float* bih = b_ih + k * 512;
    const float* bhh = b_hh + k * 512;
    const float* wih = W_ih + k * 512;
#pragma unroll
    for (int r = 0; r < 4; r++) {
        int row = ty * 4 + r;
        float xb = x[(size_t)(b0 + row) * 81 + k];
#pragma unroll
        for (int q = 0; q < 4; q++) {
            float2 ig2 = unpk(accG[0][r][q]);
            float2 fg2 = unpk(accG[1][r][q]);
            float2 gg2 = unpk(accG[2][r][q]);
            float2 og2 = unpk(accG[3][r][q]);
#pragma unroll
            for (int e = 0; e < 2; e++) {
                int col = 8 * tx + 2 * q + e;
                float igv = (e ? ig2.y : ig2.x) + bih[col]       + bhh[col]       + xb * wih[col];
                float fgv = (e ? fg2.y : fg2.x) + bih[128 + col] + bhh[128 + col] + xb * wih[128 + col];
                float ggv = (e ? gg2.y : gg2.x) + bih[256 + col] + bhh[256 + col] + xb * wih[256 + col];
                float ogv = (e ? og2.y : og2.x) + bih[384 + col] + bhh[384 + col] + xb * wih[384 + col];
                float pcv = pc_s[row * PP + col];
                float cn = sigmf(fgv) * pcv + sigmf(igv) * tanhf(ggv);
                float hn = sigmf(ogv) * tanhf(cn);
                pc_s[row * PP + col] = cn;
                ph_s[row * PP + col] = hn;
            }
        }
    }
    __syncthreads();

    // ---- coalesced writeout
    float* gh = &g_h[k][b0][0];
    float* gc = &g_c[k][b0][0];
#pragma unroll
    for (int it = 0; it < 8; it++) {
        int idx = it * 256 + tid;
        int r = idx >> 5; int c4 = (idx & 31) << 2;
        float4 vh = make_float4(ph_s[r * PP + c4],     ph_s[r * PP + c4 + 1],
                                ph_s[r * PP + c4 + 2], ph_s[r * PP + c4 + 3]);
        float4 vc = make_float4(pc_s[r * PP + c4],     pc_s[r * PP + c4 + 1],
                                pc_s[r * PP + c4 + 2], pc_s[r * PP + c4 + 3]);
        *(float4*)(gh + r * HID + c4) = vh;
        *(float4*)(gc + r * HID + c4) = vc;
    }
}

// ---------------------------------------------------------------------------
// Head kernels (unchanged — small fraction of runtime)
__global__ void z_kernel(const float* __restrict__ h_ext, const float* __restrict__ c_ext)
{
    int idx = blockIdx.x * 256 + threadIdx.x;
    int b = idx >> 8, c = idx & 255;
    float v;
    if (c < 128) v = g_h[80][b][c]       + h_ext[b * 128 + c];
    else         v = g_c[80][b][c - 128] + c_ext[b * 128 + c - 128];
    g_z[b][c] = v;
}

__global__ void __launch_bounds__(256, 1) head_gemm(
    const float* __restrict__ A, const float* __restrict__ W,
    const float* __restrict__ bias, float* __restrict__ C, int N, int K)
{
    __shared__ float A_s[64 * 33];
    __shared__ float W_s[128 * 33];
    int tid = threadIdx.x, ty = tid & 15, tx = tid >> 4;
    int b0 = blockIdx.x * 64, n0 = blockIdx.y * 128;
    float acc[4][8];
#pragma unroll
    for (int r = 0; r < 4; r++)
#pragma unroll
        for (int c = 0; c < 8; c++) acc[r][c] = 0.f;

    int nk = K >> 5;
#pragma unroll 1
    for (int kc = 0; kc < nk; kc++) {
#pragma unroll
        for (int it = 0; it < 2; it++) {
            int idx = it * 256 + tid; int r = idx >> 3; int c4 = (idx & 7) << 2;
            float4 v = *(const float4*)(A + (size_t)(b0 + r) * K + (kc << 5) + c4);
            float* p = &A_s[r * 33 + c4];
            p[0] = v.x; p[1] = v.y; p[2] = v.z; p[3] = v.w;
        }
#pragma unroll
        for (int it = 0; it < 4; it++) {
            int idx = it * 256 + tid; int n = idx >> 3; int c4 = (idx & 7) << 2;
            float4 v = *(const float4*)(W + (size_t)(n0 + n) * K + (kc << 5) + c4);
            float* p = &W_s[n * 33 + c4];
            p[0] = v.x; p[1] = v.y; p[2] = v.z; p[3] = v.w;
        }
        __syncthreads();
#pragma unroll 4
        for (int kk = 0; kk < 32; kk++) {
            float a[4], w[8];
#pragma unroll
            for (int r = 0; r < 4; r++) a[r] = A_s[(ty * 4 + r) * 33 + kk];
#pragma unroll
            for (int c = 0; c < 8; c++) w[c] = W_s[(tx * 8 + c) * 33 + kk];
#pragma unroll
            for (int r = 0; r < 4; r++)
#pragma unroll
                for (int c = 0; c < 8; c++) acc[r][c] = fmaf(a[r], w[c], acc[r][c]);
        }
        __syncthreads();
    }
#pragma unroll
    for (int r = 0; r < 4; r++)
#pragma unroll
        for (int c = 0; c < 8; c++)
            C[(size_t)(b0 + ty * 4 + r) * N + n0 + tx * 8 + c] = acc[r][c] + bias[n0 + tx * 8 + c];
}

__global__ void bn_stats_kernel(const float* __restrict__ Y, int N)
{
    __shared__ float ss[256], qq[256];
    int col = blockIdx.x, tid = threadIdx.x;
    float s = 0.f, q = 0.f;
    for (int r = tid; r < B_TOT; r += 256) {
        float v = Y[(size_t)r * N + col];
        s += v; q += v * v;
    }
    ss[tid] = s; qq[tid] = q; __syncthreads();
    for (int o = 128; o; o >>= 1) {
        if (tid < o) { ss[tid] += ss[tid + o]; qq[tid] += qq[tid + o]; }
        __syncthreads();
    }
    if (tid == 0) {
        float mu = ss[0] * (1.f / (float)B_TOT);
        float var = qq[0] * (1.f / (float)B_TOT) - mu * mu;
        g_mu[col] = mu;
        g_rstd[col] = rsqrtf(var + LN_EPS);
    }
}

__global__ void bn_relu_kernel(float* __restrict__ Y, const float* __restrict__ g,
                               const float* __restrict__ b, int N)
{
    int idx = blockIdx.x * 256 + threadIdx.x;
    int c = idx & (N - 1);
    float v = (Y[idx] - g_mu[c]) * g_rstd[c] * g[c] + b[c];
    Y[idx] = fmaxf(v, 0.f);
}

__global__ void fc3_kernel(const float* __restrict__ W, const float* __restrict__ bias)
{
    int row = (blockIdx.x * blockDim.x + threadIdx.x) >> 5;
    int lane = threadIdx.x & 31;
    float s = 0.f;
#pragma unroll
    for (int c = lane; c < 128; c += 32) s += g_y2[row][c] * W[c];
#pragma unroll
    for (int o = 16; o; o >>= 1) s += __shfl_xor_sync(0xffffffffu, s, o);
    if (lane == 0) g_y3[row] = s + bias[0];
}

__global__ void final_kernel(const float* __restrict__ g, const float* __restrict__ b,
                             float* __restrict__ out)
{
    __shared__ float ss[1024], qq[1024];
    int tid = threadIdx.x;
    float s = 0.f, q = 0.f;
    for (int r = tid; r < B_TOT; r += 1024) {
        float v = g_y3[r]; s += v; q += v * v;
    }
    ss[tid] = s; qq[tid] = q; __syncthreads();
    for (int o = 512; o; o >>= 1) {
        if (tid < o) { ss[tid] += ss[tid + o]; qq[tid] += qq[tid + o]; }
        __syncthreads();
    }
    float mu = ss[0] * (1.f / (float)B_TOT);
    float var = qq[0] * (1.f / (float)B_TOT) - mu * mu;
    float rs = rsqrtf(var + LN_EPS);
    float gg = g[0], bb = b[0];
    for (int r = tid; r < B_TOT; r += 1024) {
        float v = (g_y3[r] - mu) * rs * gg + bb;
        out[r] = 1.f / (1.f + expf(-v));
    }
}

// ---------------------------------------------------------------------------
extern "C" void kernel_launch(void* const* d_in, const int* in_sizes, int n_in,
                              void* d_out, int out_size)
{
    const float* x     = (const float*)d_in[0];
    const float* h_ext = (const float*)d_in[1];
    const float* c_ext = (const float*)d_in[2];
    const float* h_g0  = (const float*)d_in[3];
    const float* c_g0  = (const float*)d_in[4];
    const float* Wh    = (const float*)d_in[5];
    const float* bh    = (const float*)d_in[6];
    const float* Wc    = (const float*)d_in[7];
    const float* bc    = (const float*)d_in[8];
    const float* lnh_g = (const float*)d_in[9];
    const float* lnh_b = (const float*)d_in[10];
    const float* lnc_g = (const float*)d_in[11];
    const float* lnc_b = (const float*)d_in[12];
    const float* W_ih  = (const float*)d_in[13];
    const float* b_ih  = (const float*)d_in[14];
    const float* W_hh  = (const float*)d_in[15];
    const float* b_hh  = (const float*)d_in[16];
    const float* fc1W  = (const float*)d_in[17];
    const float* fc1b  = (const float*)d_in[18];
    const float* bn1g  = (const float*)d_in[19];
    const float* bn1b  = (const float*)d_in[20];
    const float* fc2W  = (const float*)d_in[21];
    const float* fc2b  = (const float*)d_in[22];
    const float* bn2g  = (const float*)d_in[23];
    const float* bn2b  = (const float*)d_in[24];
    const float* fc3W  = (const float*)d_in[25];
    const float* fc3b  = (const float*)d_in[26];
    const float* bnog  = (const float*)d_in[27];
    const float* bnob  = (const float*)d_in[28];
    float* out = (float*)d_out;

    cudaFuncSetAttribute(cell_kernel, cudaFuncAttributeMaxDynamicSharedMemorySize,
                         CELL_SMEM_BYTES);

    for (int d = 0; d <= 16; d++) {
        int ilo = d > 8 ? d - 8 : 0;
        int ihi = d < 8 ? d : 8;
        int nc = ihi - ilo + 1;
        cell_kernel<<<dim3(64, nc), 256, CELL_SMEM_BYTES>>>(
            x, h_ext, c_ext, h_g0, c_g0, Wh, bh, Wc, bc,
            lnh_g, lnh_b, lnc_g, lnc_b, W_ih, b_ih, W_hh, b_hh, d);
    }

    float *zp, *y1p, *y2p;
    cudaGetSymbolAddress((void**)&zp,  g_z);
    cudaGetSymbolAddress((void**)&y1p, g_y1);
    cudaGetSymbolAddress((void**)&y2p, g_y2);

    z_kernel<<<4096, 256>>>(h_ext, c_ext);
    head_gemm<<<dim3(64, 2), 256>>>(zp, fc1W, fc1b, y1p, 256, 256);
    bn_stats_kernel<<<256, 256>>>(y1p, 256);
    bn_relu_kernel<<<4096, 256>>>(y1p, bn1g, bn1b, 256);
    head_gemm<<<dim3(64, 1), 256>>>(y1p, fc2W, fc2b, y2p, 128, 256);
    bn_stats_kernel<<<128, 256>>>(y2p, 128);
    bn_relu_kernel<<<2048, 256>>>(y2p, bn2g, bn2b, 128);
    fc3_kernel<<<512, 256>>>(fc3W, fc3b);
    final_kernel<<<1, 1024>>>(bnog, bnob, out);
}